// round 5
// baseline (speedup 1.0000x reference)
#include <cuda_runtime.h>

#define NB   2048
#define SRC  64
#define PAD  32

// Interleaved smem tile: s[(y*64+x)*2 + 0] = fill, +1 = stroke. 32 KB.
__global__ void __launch_bounds__(512, 4)
affine_sampler_kernel(const float* __restrict__ affine,   // (N,6)
                      const float* __restrict__ fill,     // (N,64,64)
                      const float* __restrict__ stroke,   // (N,64,64)
                      float* __restrict__ out_fill,       // (N,128,128)
                      float* __restrict__ out_stroke)     // (N,128,128)
{
    __shared__ float s[SRC * SRC * 2];   // 32 KB interleaved fill/stroke

    const int n   = blockIdx.x;
    const int tid = threadIdx.x;

    // ---- stage + interleave source tiles (float4 global reads, coalesced) ----
    {
        const float4* gf = (const float4*)(fill   + (size_t)n * SRC * SRC);
        const float4* gs = (const float4*)(stroke + (size_t)n * SRC * SRC);
        #pragma unroll
        for (int i = 0; i < 2; i++) {
            const int v = tid + i * 512;          // float4 index 0..1023
            float4 f  = gf[v];
            float4 st = gs[v];
            float2* dst = (float2*)&s[v * 8];
            dst[0] = make_float2(f.x, st.x);
            dst[1] = make_float2(f.y, st.y);
            dst[2] = make_float2(f.z, st.z);
            dst[3] = make_float2(f.w, st.w);
        }
    }

    // ---- theta (broadcast loads; every thread computes) ----
    const float* a = affine + n * 6;
    const float a00 = 2.0f / (1.0f + __expf(-a[0]));
    const float a11 = 2.0f / (1.0f + __expf(-a[1]));
    const float a01 = 2.0f * tanhf(a[2]);
    const float a10 = 2.0f * tanhf(a[3]);
    const float a02 = tanhf(a[4]);
    const float a12 = tanhf(a[5]);

    // Folded chain: ix = a00*x + a01*y + Cx  (pixel coords in padded 128x128 img)
    const float Cx = 64.0f * a02 + 63.5f - 63.5f * (a00 + a01);
    const float Cy = 64.0f * a12 + 63.5f - 63.5f * (a10 + a11);

    // row-endpoint deltas (x = 0 .. 127); a00 > 0 always, a10 sign unknown
    const float ex = 127.0f * a00;
    const float ey = 127.0f * a10;

    __syncthreads();

    float* of = out_fill   + (size_t)n * 128 * 128;
    float* os = out_stroke + (size_t)n * 128 * 128;

    const int lane = tid & 31;
    const int warp = tid >> 5;              // 0..15; warp owns whole rows
    const float xf = (float)(lane << 2);    // 4 contiguous pixels per lane

    #pragma unroll 1
    for (int it = 0; it < 8; it++) {
        const int   row = it * 16 + warp;
        const float yf  = (float)row;

        // row-start coords (x=0)
        const float rx0 = fmaf(a01, yf, Cx);
        const float ry0 = fmaf(a11, yf, Cy);
        // row extremes over x in [0,127]
        const float lox = rx0;               // a00 > 0
        const float hix = rx0 + ex;
        const float loy = fminf(ry0, ry0 + ey);
        const float hiy = fmaxf(ry0, ry0 + ey);

        // warp-uniform classification (no ballot needed), with fp-safety margins
        const bool inside = (lox >= 32.01f) & (hix <= 94.99f) &
                            (loy >= 32.01f) & (hiy <= 94.99f);
        const bool zero   = (hix <= 30.99f) | (lox >= 96.01f) |
                            (hiy <= 30.99f) | (loy >= 96.01f);

        const int o = row * 128 + (lane << 2);

        float ix = fmaf(a00, xf, rx0);
        float iy = fmaf(a10, xf, ry0);

        float4 rf, rs;
        float* rfp = &rf.x;
        float* rsp = &rs.x;

        if (inside) {
            // ---- fast interior path: no bounds checks, no predication ----
            #pragma unroll
            for (int k = 0; k < 4; k++) {
                const float fx0 = floorf(ix);
                const float fy0 = floorf(iy);
                const float wx = ix - fx0;
                const float wy = iy - fy0;
                const float mx = 1.0f - wx;
                const float my = 1.0f - wy;

                // (y0-32)*64 + (x0-32), in float2 units: fy0*64+fx0 - 2080 (exact < 2^24)
                const int base = (__float2int_rn(fmaf(fy0, 64.0f, fx0)) - 2080) * 2;
                const float2 r00 = *(const float2*)&s[base];
                const float2 r10 = *(const float2*)&s[base + 2];
                const float2 r01 = *(const float2*)&s[base + 128];
                const float2 r11 = *(const float2*)&s[base + 130];

                const float w00 = mx * my, w10 = wx * my;
                const float w01 = mx * wy, w11 = wx * wy;

                float fv = r00.x * w00, sv = r00.y * w00;
                fv = fmaf(r10.x, w10, fv); sv = fmaf(r10.y, w10, sv);
                fv = fmaf(r01.x, w01, fv); sv = fmaf(r01.y, w01, sv);
                fv = fmaf(r11.x, w11, fv); sv = fmaf(r11.y, w11, sv);

                rfp[k] = fv;
                rsp[k] = sv;
                ix += a00;
                iy += a10;
            }
            __stcs((float4*)&of[o], rf);
            __stcs((float4*)&os[o], rs);
        } else if (zero) {
            // ---- all-zero row: just store zeros ----
            const float4 z = make_float4(0.f, 0.f, 0.f, 0.f);
            __stcs((float4*)&of[o], z);
            __stcs((float4*)&os[o], z);
        } else {
            // ---- generic boundary path (predicated taps) ----
            #pragma unroll
            for (int k = 0; k < 4; k++) {
                const int x0 = __float2int_rd(ix);
                const int y0 = __float2int_rd(iy);
                const float wx = ix - (float)x0;
                const float wy = iy - (float)y0;
                const float mx = 1.0f - wx;
                const float my = 1.0f - wy;

                const bool vx0 = (unsigned)(x0 - PAD)     < 64u;
                const bool vx1 = (unsigned)(x0 - PAD + 1) < 64u;
                const bool vy0 = (unsigned)(y0 - PAD)     < 64u;
                const bool vy1 = (unsigned)(y0 - PAD + 1) < 64u;

                const int base = ((y0 - PAD) * SRC + (x0 - PAD)) * 2;

                float fv = 0.0f, sv = 0.0f;
                if (vx0 & vy0) { float2 r = *(const float2*)&s[base];       float w = mx * my; fv = fmaf(r.x, w, fv); sv = fmaf(r.y, w, sv); }
                if (vx1 & vy0) { float2 r = *(const float2*)&s[base + 2];   float w = wx * my; fv = fmaf(r.x, w, fv); sv = fmaf(r.y, w, sv); }
                if (vx0 & vy1) { float2 r = *(const float2*)&s[base + 128]; float w = mx * wy; fv = fmaf(r.x, w, fv); sv = fmaf(r.y, w, sv); }
                if (vx1 & vy1) { float2 r = *(const float2*)&s[base + 130]; float w = wx * wy; fv = fmaf(r.x, w, fv); sv = fmaf(r.y, w, sv); }

                rfp[k] = fv;
                rsp[k] = sv;
                ix += a00;
                iy += a10;
            }
            __stcs((float4*)&of[o], rf);
            __stcs((float4*)&os[o], rs);
        }
    }
}

extern "C" void kernel_launch(void* const* d_in, const int* in_sizes, int n_in,
                              void* d_out, int out_size) {
    const float* affine = (const float*)d_in[0];   // (N,6) fp32
    const float* fill   = (const float*)d_in[1];   // (N,64,64) fp32
    const float* stroke = (const float*)d_in[2];   // (N,64,64) fp32
    // d_in[3] = targetsize (constant, unused)

    float* out_fill   = (float*)d_out;
    float* out_stroke = (float*)d_out + (size_t)NB * 128 * 128;

    affine_sampler_kernel<<<NB, 512>>>(affine, fill, stroke, out_fill, out_stroke);
}